// round 8
// baseline (speedup 1.0000x reference)
#include <cuda_runtime.h>

#define NBLOCKS 1184
#define NTHREADS 256

__device__ float        g_partials[NBLOCKS];
__device__ unsigned int g_counter = 0;   // self-resetting via atomicInc wrap

__global__ __launch_bounds__(NTHREADS, 8)
void qsum_fused_kernel(const float* __restrict__ phi,
                       const float* __restrict__ w,
                       long long n4, long long n_total,
                       float bias, float inv_N,
                       float* __restrict__ out) {
    const float4* __restrict__ p4 = reinterpret_cast<const float4*>(phi);
    const float4* __restrict__ w4 = reinterpret_cast<const float4*>(w);

    float acc = 0.0f;
    const long long tid    = (long long)blockIdx.x * NTHREADS + threadIdx.x;
    const long long stride = (long long)gridDim.x * NTHREADS;

    // Grid-stride loop: 2x LDG.128 per iter. Empirically optimal on this
    // part — runs at the LTS service-rate ceiling (~6.1 TB/s). All tested
    // alternatives (unroll, ldcs, SW pipeline, contiguous tiling) were
    // neutral or worse; the 268 MB stream is the irreducible cost.
    for (long long i = tid; i < n4; i += stride) {
        float4 a = p4[i];
        float4 b = w4[i];
        acc += __cosf(a.x * b.x);
        acc += __cosf(a.y * b.y);
        acc += __cosf(a.z * b.z);
        acc += __cosf(a.w * b.w);
    }

    // Scalar tail (only when n_total % 4 != 0; C=2^25 makes this empty,
    // kept for generality)
    const long long ti = n4 * 4 + tid;
    if (ti < n_total) {
        acc += __cosf(phi[ti] * w[ti]);
    }

    // Warp reduce
    #pragma unroll
    for (int o = 16; o > 0; o >>= 1)
        acc += __shfl_xor_sync(0xffffffffu, acc, o);

    __shared__ float smem[NTHREADS / 32];
    if ((threadIdx.x & 31) == 0)
        smem[threadIdx.x >> 5] = acc;
    __syncthreads();

    // Block partial -> global, then last block finishes (fused final pass)
    __shared__ bool s_is_last;
    if (threadIdx.x == 0) {
        float v = 0.0f;
        #pragma unroll
        for (int k = 0; k < NTHREADS / 32; k++)
            v += smem[k];
        g_partials[blockIdx.x] = v;
        __threadfence();
        // atomicInc wraps to 0 when old == NBLOCKS-1 -> ready for next replay
        unsigned int ticket = atomicInc(&g_counter, NBLOCKS - 1);
        s_is_last = (ticket == NBLOCKS - 1);
    }
    __syncthreads();

    if (s_is_last) {
        // Deterministic final reduction: fixed strided assignment + fixed tree
        float v = 0.0f;
        for (int k = threadIdx.x; k < NBLOCKS; k += NTHREADS)
            v += g_partials[k];

        #pragma unroll
        for (int o = 16; o > 0; o >>= 1)
            v += __shfl_xor_sync(0xffffffffu, v, o);

        if ((threadIdx.x & 31) == 0)
            smem[threadIdx.x >> 5] = v;
        __syncthreads();

        if (threadIdx.x < 32) {
            float t = (threadIdx.x < NTHREADS / 32) ? smem[threadIdx.x] : 0.0f;
            #pragma unroll
            for (int o = 4; o > 0; o >>= 1)
                t += __shfl_xor_sync(0xffffffffu, t, o);
            if (threadIdx.x == 0)
                out[0] = (t + bias) * inv_N;
        }
    }
}

extern "C" void kernel_launch(void* const* d_in, const int* in_sizes, int n_in,
                              void* d_out, int out_size) {
    const float* phi = (const float*)d_in[0];
    const float* w   = (const float*)d_in[1];

    long long C = (long long)in_sizes[0];

    // N = 2^ceil(log2(C))
    int n = 0;
    while ((1LL << n) < C) n++;
    long long N = 1LL << n;

    float bias  = (float)(double)(N - C);
    float inv_N = (float)(1.0 / (double)N);

    long long n4 = C / 4;

    qsum_fused_kernel<<<NBLOCKS, NTHREADS>>>(phi, w, n4, C, bias, inv_N,
                                             (float*)d_out);
}

// round 11
// speedup vs baseline: 1.0007x; 1.0007x over previous
#include <cuda_runtime.h>

#define NBLOCKS 1184
#define NTHREADS 256

__device__ float        g_partials[NBLOCKS];
__device__ unsigned int g_counter = 0;   // self-resetting via atomicInc wrap

// 256-bit global load (Blackwell sm_100+): one LDG.E.256 fills 8 floats.
__device__ __forceinline__ void ldg256(const float* p,
                                       float& v0, float& v1, float& v2, float& v3,
                                       float& v4, float& v5, float& v6, float& v7) {
    asm volatile("ld.global.nc.v8.f32 {%0,%1,%2,%3,%4,%5,%6,%7}, [%8];"
                 : "=f"(v0), "=f"(v1), "=f"(v2), "=f"(v3),
                   "=f"(v4), "=f"(v5), "=f"(v6), "=f"(v7)
                 : "l"(p));
}

__global__ __launch_bounds__(NTHREADS, 8)
void qsum_fused_kernel(const float* __restrict__ phi,
                       const float* __restrict__ w,
                       long long n8, long long n_total,
                       float bias, float inv_N,
                       float* __restrict__ out) {
    float acc = 0.0f;
    const long long tid    = (long long)blockIdx.x * NTHREADS + threadIdx.x;
    const long long stride = (long long)gridDim.x * NTHREADS;

    // Grid-stride loop: 2x LDG.256 per iter (8 elements per array).
    for (long long i = tid; i < n8; i += stride) {
        const float* pa = phi + i * 8;
        const float* pb = w   + i * 8;
        float a0, a1, a2, a3, a4, a5, a6, a7;
        float b0, b1, b2, b3, b4, b5, b6, b7;
        ldg256(pa, a0, a1, a2, a3, a4, a5, a6, a7);
        ldg256(pb, b0, b1, b2, b3, b4, b5, b6, b7);
        acc += __cosf(a0 * b0);
        acc += __cosf(a1 * b1);
        acc += __cosf(a2 * b2);
        acc += __cosf(a3 * b3);
        acc += __cosf(a4 * b4);
        acc += __cosf(a5 * b5);
        acc += __cosf(a6 * b6);
        acc += __cosf(a7 * b7);
    }

    // Scalar tail (n_total not multiple of 8; empty for C=2^25, kept general)
    for (long long ti = n8 * 8 + tid; ti < n_total; ti += stride) {
        acc += __cosf(phi[ti] * w[ti]);
    }

    // Warp reduce
    #pragma unroll
    for (int o = 16; o > 0; o >>= 1)
        acc += __shfl_xor_sync(0xffffffffu, acc, o);

    __shared__ float smem[NTHREADS / 32];
    if ((threadIdx.x & 31) == 0)
        smem[threadIdx.x >> 5] = acc;
    __syncthreads();

    // Block partial -> global, then last block finishes (fused final pass)
    __shared__ bool s_is_last;
    if (threadIdx.x == 0) {
        float v = 0.0f;
        #pragma unroll
        for (int k = 0; k < NTHREADS / 32; k++)
            v += smem[k];
        g_partials[blockIdx.x] = v;
        __threadfence();
        // atomicInc wraps to 0 when old == NBLOCKS-1 -> ready for next replay
        unsigned int ticket = atomicInc(&g_counter, NBLOCKS - 1);
        s_is_last = (ticket == NBLOCKS - 1);
    }
    __syncthreads();

    if (s_is_last) {
        // Deterministic final reduction: fixed strided assignment + fixed tree
        float v = 0.0f;
        for (int k = threadIdx.x; k < NBLOCKS; k += NTHREADS)
            v += g_partials[k];

        #pragma unroll
        for (int o = 16; o > 0; o >>= 1)
            v += __shfl_xor_sync(0xffffffffu, v, o);

        if ((threadIdx.x & 31) == 0)
            smem[threadIdx.x >> 5] = v;
        __syncthreads();

        if (threadIdx.x < 32) {
            float t = (threadIdx.x < NTHREADS / 32) ? smem[threadIdx.x] : 0.0f;
            #pragma unroll
            for (int o = 4; o > 0; o >>= 1)
                t += __shfl_xor_sync(0xffffffffu, t, o);
            if (threadIdx.x == 0)
                out[0] = (t + bias) * inv_N;
        }
    }
}

extern "C" void kernel_launch(void* const* d_in, const int* in_sizes, int n_in,
                              void* d_out, int out_size) {
    const float* phi = (const float*)d_in[0];
    const float* w   = (const float*)d_in[1];

    long long C = (long long)in_sizes[0];

    // N = 2^ceil(log2(C))
    int n = 0;
    while ((1LL << n) < C) n++;
    long long N = 1LL << n;

    float bias  = (float)(double)(N - C);
    float inv_N = (float)(1.0 / (double)N);

    long long n8 = C / 8;

    qsum_fused_kernel<<<NBLOCKS, NTHREADS>>>(phi, w, n8, C, bias, inv_N,
                                             (float*)d_out);
}

// round 12
// speedup vs baseline: 1.0085x; 1.0077x over previous
#include <cuda_runtime.h>

#define NBLOCKS 1216   // 152 SMs (GB300) x 8 CTAs/SM — perfectly balanced wave
#define NTHREADS 256

__device__ float        g_partials[NBLOCKS];
__device__ unsigned int g_counter = 0;   // self-resetting via atomicInc wrap

// 256-bit global load (Blackwell sm_100+): one LDG.E.256 fills 8 floats.
__device__ __forceinline__ void ldg256(const float* p,
                                       float& v0, float& v1, float& v2, float& v3,
                                       float& v4, float& v5, float& v6, float& v7) {
    asm volatile("ld.global.nc.v8.f32 {%0,%1,%2,%3,%4,%5,%6,%7}, [%8];"
                 : "=f"(v0), "=f"(v1), "=f"(v2), "=f"(v3),
                   "=f"(v4), "=f"(v5), "=f"(v6), "=f"(v7)
                 : "l"(p));
}

__global__ __launch_bounds__(NTHREADS, 8)
void qsum_fused_kernel(const float* __restrict__ phi,
                       const float* __restrict__ w,
                       long long n8, long long n_total,
                       float bias, float inv_N,
                       float* __restrict__ out) {
    float acc = 0.0f;
    const long long tid    = (long long)blockIdx.x * NTHREADS + threadIdx.x;
    const long long stride = (long long)gridDim.x * NTHREADS;

    // Grid-stride loop: 2x LDG.256 per iter (8 elements per array).
    for (long long i = tid; i < n8; i += stride) {
        const float* pa = phi + i * 8;
        const float* pb = w   + i * 8;
        float a0, a1, a2, a3, a4, a5, a6, a7;
        float b0, b1, b2, b3, b4, b5, b6, b7;
        ldg256(pa, a0, a1, a2, a3, a4, a5, a6, a7);
        ldg256(pb, b0, b1, b2, b3, b4, b5, b6, b7);
        acc += __cosf(a0 * b0);
        acc += __cosf(a1 * b1);
        acc += __cosf(a2 * b2);
        acc += __cosf(a3 * b3);
        acc += __cosf(a4 * b4);
        acc += __cosf(a5 * b5);
        acc += __cosf(a6 * b6);
        acc += __cosf(a7 * b7);
    }

    // Scalar tail (n_total not multiple of 8; empty for C=2^25, kept general)
    for (long long ti = n8 * 8 + tid; ti < n_total; ti += stride) {
        acc += __cosf(phi[ti] * w[ti]);
    }

    // Warp reduce
    #pragma unroll
    for (int o = 16; o > 0; o >>= 1)
        acc += __shfl_xor_sync(0xffffffffu, acc, o);

    __shared__ float smem[NTHREADS / 32];
    if ((threadIdx.x & 31) == 0)
        smem[threadIdx.x >> 5] = acc;
    __syncthreads();

    // Block partial -> global, then last block finishes (fused final pass)
    __shared__ bool s_is_last;
    if (threadIdx.x == 0) {
        float v = 0.0f;
        #pragma unroll
        for (int k = 0; k < NTHREADS / 32; k++)
            v += smem[k];
        g_partials[blockIdx.x] = v;
        __threadfence();
        // atomicInc wraps to 0 when old == NBLOCKS-1 -> ready for next replay
        unsigned int ticket = atomicInc(&g_counter, NBLOCKS - 1);
        s_is_last = (ticket == NBLOCKS - 1);
    }
    __syncthreads();

    if (s_is_last) {
        // Deterministic final reduction: fixed strided assignment + fixed tree
        float v = 0.0f;
        for (int k = threadIdx.x; k < NBLOCKS; k += NTHREADS)
            v += g_partials[k];

        #pragma unroll
        for (int o = 16; o > 0; o >>= 1)
            v += __shfl_xor_sync(0xffffffffu, v, o);

        if ((threadIdx.x & 31) == 0)
            smem[threadIdx.x >> 5] = v;
        __syncthreads();

        if (threadIdx.x < 32) {
            float t = (threadIdx.x < NTHREADS / 32) ? smem[threadIdx.x] : 0.0f;
            #pragma unroll
            for (int o = 4; o > 0; o >>= 1)
                t += __shfl_xor_sync(0xffffffffu, t, o);
            if (threadIdx.x == 0)
                out[0] = (t + bias) * inv_N;
        }
    }
}

extern "C" void kernel_launch(void* const* d_in, const int* in_sizes, int n_in,
                              void* d_out, int out_size) {
    const float* phi = (const float*)d_in[0];
    const float* w   = (const float*)d_in[1];

    long long C = (long long)in_sizes[0];

    // N = 2^ceil(log2(C))
    int n = 0;
    while ((1LL << n) < C) n++;
    long long N = 1LL << n;

    float bias  = (float)(double)(N - C);
    float inv_N = (float)(1.0 / (double)N);

    long long n8 = C / 8;

    qsum_fused_kernel<<<NBLOCKS, NTHREADS>>>(phi, w, n8, C, bias, inv_N,
                                             (float*)d_out);
}